// round 17
// baseline (speedup 1.0000x reference)
#include <cuda_runtime.h>
#include <cuda_fp16.h>

// ROIAlign via NHWC-fp16 pre-transpose (serial two-kernel):
//   K1: features (2,256,200,304) fp32 NCHW -> g_nhwc (2, 200*304, 256) fp16
//   K2: gather, block = (box, bin-half) -> grid 2000 (2.7 waves at 5
//       blocks/SM vs 1.35 waves at grid 1000: kills the 48% wave tail).
//       Resource settings proven in R15 kept EXACTLY: __launch_bounds__(256,5)
//       (48 regs -> 4x uint4 load batches intact), fp16 staging, half2 math.
// spatial_scale=0.25, sampling_ratio=2, output (1000,256,7,7) fp32.

namespace {

constexpr int C_DIM = 256;
constexpr int H_DIM = 200;
constexpr int W_DIM = 304;
constexpr int S_DIM = H_DIM * W_DIM;        // 60800
constexpr int PH = 7, PW = 7;
constexpr int BINS = PH * PW;               // 49
constexpr float SCALE = 0.25f;
constexpr int S_TILES = S_DIM / 32;         // 1900
constexpr int BPB = 25;                     // max bins per block (25 / 24)
constexpr int SM_PITCH_H = 264;             // halves per staged bin row
                                            // (>=256; stride 528B = 33*16B)

__device__ __half g_nhwc[2ull * S_DIM * C_DIM];   // 62.3 MB scratch

__device__ __forceinline__ void axis_interp(float coord, int size,
                                            int& lo, int& hi,
                                            float& frac, bool& valid) {
    valid = (coord >= -1.0f) && (coord <= (float)size);
    float c = fmaxf(coord, 0.0f);
    int low = (int)c;
    if (low >= size - 1) { lo = size - 1; hi = size - 1; frac = 0.0f; }
    else                 { lo = low;      hi = low + 1;  frac = c - (float)low; }
}

// ---------------- K1: NCHW fp32 -> NHWC fp16 transpose ----------------
// Tile: 64 channels x 32 spatial. Reads coalesced along spatial (128B),
// writes coalesced along channel (uint = 2 halves per lane, 128B rows).
__global__ __launch_bounds__(256)
void transpose_kernel(const float* __restrict__ feat) {
    __shared__ __half tile[32][66];     // [spatial][channel], +2 pad

    int bid = blockIdx.x;
    int ct  = bid & 3;                  // 4 channel tiles of 64
    int st  = (bid >> 2) % S_TILES;
    int n   = bid / (4 * S_TILES);
    int c0  = ct * 64;
    int s0  = st * 32;

    int lane = threadIdx.x & 31;
    int grp  = threadIdx.x >> 5;        // 0..7

    const float* src = feat + ((size_t)(n * C_DIM + c0)) * S_DIM + s0;
#pragma unroll
    for (int it = 0; it < 8; it++) {
        int c = it * 8 + grp;
        tile[lane][c] = __float2half(src[(size_t)c * S_DIM + lane]);
    }
    __syncthreads();

    const unsigned* tw = (const unsigned*)&tile[0][0];   // 33 words per row
    unsigned* dst = (unsigned*)(g_nhwc + ((size_t)n * S_DIM + s0) * C_DIM + c0);
#pragma unroll
    for (int it = 0; it < 4; it++) {
        int s = it * 8 + grp;
        dst[(size_t)s * (C_DIM / 2) + lane] = tw[s * 33 + lane];
    }
}

// ---------------- K2: gather ----------------
// Block = (box, bin-half h): bins [25h, min(25h+25, 49)). 8 warps; warp w
// handles a contiguous run of 3-4 local bins. Lane = channels lane*8..+7
// via one uint4 (8 fp16): full 256-channel corner in ONE 512B transaction.
__global__ __launch_bounds__(256, 5)
void gather_kernel(const float* __restrict__ boxes,
                   float* __restrict__ out) {
    __shared__ __half smh[BPB * SM_PITCH_H];    // 13.2 KB

    int bid  = blockIdx.x;
    int r    = bid >> 1;                    // box
    int h    = bid & 1;                     // bin half
    int s0   = h * BPB;                     // first global bin
    int nbin = h ? (BINS - BPB) : BPB;      // 24 : 25

    int tid  = threadIdx.x;
    int lane = tid & 31;
    int w    = tid >> 5;

    const float* bx = boxes + (size_t)r * 5;
    int   nb = (int)__ldg(bx + 0);
    float x1 = __ldg(bx + 1) * SCALE;
    float y1 = __ldg(bx + 2) * SCALE;
    float x2 = __ldg(bx + 3) * SCALE;
    float y2 = __ldg(bx + 4) * SCALE;
    float bin_w = fmaxf(x2 - x1, 1.0f) * (1.0f / PW);
    float bin_h = fmaxf(y2 - y1, 1.0f) * (1.0f / PH);

    const __half* base = g_nhwc + (size_t)nb * S_DIM * C_DIM + (lane << 3);

    // Contiguous bin run per warp: warp w does [lo, hi).
    int lo = (w * nbin) >> 3;
    int hi = ((w + 1) * nbin) >> 3;

    for (int sl = lo; sl < hi; sl++) {
        int s  = s0 + sl;
        int ph = s / PW, pw = s % PW;

        // 4 candidate rows (2 samples x lo/hi) and 4 candidate cols with
        // axis validity folded into the weights; 0.25 sample-mean folded
        // into wy. All lane-uniform.
        int   ro[4], xo[4];
        float wy[4], wx[4];
#pragma unroll
        for (int i = 0; i < 2; i++) {
            float yc = y1 + ((float)ph + ((float)i + 0.5f) * 0.5f) * bin_h;
            float xc = x1 + ((float)pw + ((float)i + 0.5f) * 0.5f) * bin_w;
            int yl, yh, xl, xh; float fy, fx; bool vy, vx;
            axis_interp(yc, H_DIM, yl, yh, fy, vy);
            axis_interp(xc, W_DIM, xl, xh, fx, vx);
            ro[2 * i]     = (yl * W_DIM) * C_DIM;
            ro[2 * i + 1] = (yh * W_DIM) * C_DIM;
            wy[2 * i]     = vy ? (1.0f - fy) * 0.25f : 0.0f;
            wy[2 * i + 1] = vy ? fy * 0.25f          : 0.0f;
            xo[2 * i]     = xl * C_DIM;
            xo[2 * i + 1] = xh * C_DIM;
            wx[2 * i]     = vx ? (1.0f - fx) : 0.0f;
            wx[2 * i + 1] = vx ? fx          : 0.0f;
        }

        float a0 = 0.f, a1 = 0.f, a2 = 0.f, a3 = 0.f;
        float a4 = 0.f, a5 = 0.f, a6 = 0.f, a7 = 0.f;

        // One sample-row per batch: 4 independent uint4 loads issued
        // back-to-back. Within-row accumulation in half2 (4-FMA chains on
        // partials <= 0.25 -> bounded rounding), promoted to fp32 per row.
#pragma unroll
        for (int a = 0; a < 4; a++) {
            const __half* rp = base + ro[a];
            uint4 v[4];
#pragma unroll
            for (int b2 = 0; b2 < 4; b2++)
                v[b2] = __ldg((const uint4*)(rp + xo[b2]));

            __half2 r0 = __float2half2_rn(0.f);
            __half2 r1 = r0, r2 = r0, r3 = r0;
#pragma unroll
            for (int b2 = 0; b2 < 4; b2++) {
                __half2 w2 = __float2half2_rn(wy[a] * wx[b2]);
                r0 = __hfma2(w2, *(const __half2*)&v[b2].x, r0);
                r1 = __hfma2(w2, *(const __half2*)&v[b2].y, r1);
                r2 = __hfma2(w2, *(const __half2*)&v[b2].z, r2);
                r3 = __hfma2(w2, *(const __half2*)&v[b2].w, r3);
            }
            float2 f0 = __half22float2(r0);
            float2 f1 = __half22float2(r1);
            float2 f2 = __half22float2(r2);
            float2 f3 = __half22float2(r3);
            a0 += f0.x;  a1 += f0.y;
            a2 += f1.x;  a3 += f1.y;
            a4 += f2.x;  a5 += f2.y;
            a6 += f3.x;  a7 += f3.y;
        }

        // Stage channels lane*8..+7 as fp16: one 16B uint4 STS per lane
        // (row stride 528B + lane offset 16B -> aligned, conflict-free).
        uint4 pk;
        __half2 h0 = __floats2half2_rn(a0, a1);
        __half2 h1 = __floats2half2_rn(a2, a3);
        __half2 h2 = __floats2half2_rn(a4, a5);
        __half2 h3 = __floats2half2_rn(a6, a7);
        pk.x = *(const unsigned*)&h0;
        pk.y = *(const unsigned*)&h1;
        pk.z = *(const unsigned*)&h2;
        pk.w = *(const unsigned*)&h3;
        ((uint4*)(smh + sl * SM_PITCH_H))[lane] = pk;
    }
    __syncthreads();

    // Epilogue: this block's (256 ch x nbin bins) slice of the output;
    // sb fast -> contiguous 25(24)-float runs per channel (coalesced STG).
    float* o = out + (size_t)r * (C_DIM * BINS) + s0;
    int total = C_DIM * nbin;
    for (int q = tid; q < total; q += 256) {
        int c  = q / nbin;
        int sb = q - c * nbin;
        o[c * BINS + sb] = __half2float(smh[sb * SM_PITCH_H + c]);
    }
}

} // namespace

extern "C" void kernel_launch(void* const* d_in, const int* in_sizes, int n_in,
                              void* d_out, int out_size) {
    const float* features = (const float*)d_in[0];
    const float* boxes    = (const float*)d_in[1];
    float*       out      = (float*)d_out;

    int R = in_sizes[1] / 5;                          // 1000 boxes

    int tblocks = 2 * 4 * S_TILES;                    // 15200
    transpose_kernel<<<tblocks, 256>>>(features);
    gather_kernel<<<2 * R, 256>>>(boxes, out);
}